// round 5
// baseline (speedup 1.0000x reference)
#include <cuda_runtime.h>

// TemporalAttentionModel: B=16, T=48, N=500, D=64, K=8 heads, d=8
// Fused per-(b,n) kernel. fp32 FFMA2 with duplicated-operand smem layout
// (no pack movs in GEMM inner loops), 768 threads, 2-D warp tiling.

#define B_  16
#define T_  48
#define N_  500
#define NTHR 768

#define HPAD 130   // u64 stride per Hdup row   (48 rows)
#define QPAD 68    // float stride per q/k/v row (48 rows each), 16B-aligned rows
#define APAD 66    // u64 stride per aos_dup / Zdup row

typedef unsigned long long u64;

__device__ __forceinline__ u64 pack2(float x, float y) {
    u64 r; asm("mov.b64 %0, {%1, %2};" : "=l"(r) : "f"(x), "f"(y)); return r;
}
__device__ __forceinline__ void unpack2(u64 v, float& x, float& y) {
    asm("mov.b64 {%0, %1}, %2;" : "=f"(x), "=f"(y) : "l"(v));
}
__device__ __forceinline__ u64 fma2(u64 a, u64 b, u64 c) {
    u64 d; asm("fma.rn.f32x2 %0, %1, %2, %3;" : "=l"(d) : "l"(a), "l"(b), "l"(c)); return d;
}

// ---- shared memory layout (float units) ----
// [0, 12480)          : Hdup  48 x HPAD u64      -> reused as aos_dup (48 x APAD u64)
// [12480, 37056)      : Ws 128x192 QKV weights   -> reused: W15 [0,4096), W16 [4096,8192),
//                                                   Zdup (48 x APAD u64) at +8192 floats
// [37056, 46848)      : qkv  3 x 48 x QPAD
// [46848, 47168)      : biases (192 + 64 + 64)
#define OFF_WS   12480
#define OFF_QKV  37056
#define OFF_BIAS 46848
static const int SMEM_FLOATS = 47168;
static const int SMEM_BYTES  = SMEM_FLOATS * 4;   // 188,672 B -> 1 CTA/SM, 24 warps

__global__ __launch_bounds__(NTHR, 1)
void fused_temporal_attn(const float* __restrict__ X, const float* __restrict__ STE,
                         const float* __restrict__ W12, const float* __restrict__ b12,
                         const float* __restrict__ W13, const float* __restrict__ b13,
                         const float* __restrict__ W14, const float* __restrict__ b14,
                         const float* __restrict__ W15, const float* __restrict__ b15,
                         const float* __restrict__ W16, const float* __restrict__ b16,
                         float* __restrict__ out)
{
    extern __shared__ float sm[];
    u64*   Hdup  = (u64*)sm;                 // 48 x HPAD
    float* Ws    = sm + OFF_WS;              // 128 x 192
    float* qkv   = sm + OFF_QKV;             // q | k | v, each 48 x QPAD
    float* biasq = sm + OFF_BIAS;            // 192
    float* b15s  = biasq + 192;              // 64
    float* b16s  = b15s + 64;                // 64
    u64*   aosd  = (u64*)sm;                 // 48 x APAD (over Hdup, after stage 2)
    u64*   Zdup  = (u64*)(Ws + 8192);        // 48 x APAD (over Ws tail, after stage 4)
    float* W15s  = Ws;                       // 64 x 64
    float* W16s  = Ws + 4096;                // 64 x 64

    const int n   = blockIdx.x;
    const int b   = blockIdx.y;
    const int tid = threadIdx.x;

    // 2-D warp-internal tiling used by GEMM stages:
    const int lane = tid & 31;
    const int warp = tid >> 5;               // 0..23
    const int csub = lane & 7;               // 8 col-subs  (distinct within warp)
    const int rsub = lane >> 3;              // 4 row-subs  (distinct within warp)
    const int wc   = warp & 3;               // 4
    const int wr   = warp >> 2;              // 6
    const int cg   = wc * 8 + csub;          // 0..31
    const int rg   = wr * 4 + rsub;          // 0..23

    // ------------------------------------------------------------------
    // Stage 1: load H (duplicated), QKV weights, biases
    // ------------------------------------------------------------------
    {
        const float4* X4   = (const float4*)X;
        const float4* STE4 = (const float4*)STE;
        {   // 768 float4 items, exactly one per thread (+ its STE twin)
            int t = tid >> 4;                // 0..47
            int c = tid & 15;                // 0..15 (float4 units)
            int base = ((b * T_ + t) * N_ + n) * 16 + c;
            float4 vx = X4[base];
            float4 vs = STE4[base];
            u64* hrow = &Hdup[t * HPAD];
            int c4 = c * 4;
            *(ulonglong2*)&hrow[c4]          = make_ulonglong2(pack2(vx.x, vx.x), pack2(vx.y, vx.y));
            *(ulonglong2*)&hrow[c4 + 2]      = make_ulonglong2(pack2(vx.z, vx.z), pack2(vx.w, vx.w));
            *(ulonglong2*)&hrow[64 + c4]     = make_ulonglong2(pack2(vs.x, vs.x), pack2(vs.y, vs.y));
            *(ulonglong2*)&hrow[64 + c4 + 2] = make_ulonglong2(pack2(vs.z, vs.z), pack2(vs.w, vs.w));
        }
        // Ws[i*192 + m*64 + j] = Wm[i*64 + j]; 6144 float4, 8 per thread
        const float4* Wsrc[3] = { (const float4*)W12, (const float4*)W13, (const float4*)W14 };
        float4* W4 = (float4*)Ws;
        #pragma unroll
        for (int it = 0; it < 8; it++) {
            int id = tid + it * NTHR;
            int i  = id / 48;
            int r  = id - i * 48;
            int m  = r >> 4;
            int j4 = r & 15;
            W4[i * 48 + r] = Wsrc[m][i * 16 + j4];
        }
        if (tid < 64) {
            biasq[tid]       = b12[tid];
            biasq[64 + tid]  = b13[tid];
            biasq[128 + tid] = b14[tid];
            b15s[tid]        = b15[tid];
            b16s[tid]        = b16[tid];
        }
    }
    __syncthreads();

    // ------------------------------------------------------------------
    // Stage 2: QKV = relu(H @ [W12|W13|W14] + bias)  [48 x 192]
    // Thread tile: 2 rows x 6 cols (3 FFMA2 col-pairs). No pack movs.
    // ------------------------------------------------------------------
    {
        const int r0 = rg * 2;
        const int c0 = cg * 6;
        u64 acc0[3], acc1[3];
        #pragma unroll
        for (int p = 0; p < 3; p++) {
            u64 bp = *(const u64*)&biasq[c0 + 2 * p];
            acc0[p] = bp; acc1[p] = bp;
        }
        const u64* ha_base = &Hdup[r0 * HPAD];
        const u64* hb_base = &Hdup[(r0 + 1) * HPAD];

        #pragma unroll 4
        for (int i = 0; i < 128; i += 2) {
            ulonglong2 ha = *(const ulonglong2*)&ha_base[i];
            ulonglong2 hb = *(const ulonglong2*)&hb_base[i];
            const float* w0r = &Ws[i * 192 + c0];
            const float* w1r = w0r + 192;
            u64 wa0 = *(const u64*)&w0r[0], wa1 = *(const u64*)&w0r[2], wa2 = *(const u64*)&w0r[4];
            u64 wb0 = *(const u64*)&w1r[0], wb1 = *(const u64*)&w1r[2], wb2 = *(const u64*)&w1r[4];
            acc0[0] = fma2(ha.x, wa0, acc0[0]);  acc1[0] = fma2(hb.x, wa0, acc1[0]);
            acc0[1] = fma2(ha.x, wa1, acc0[1]);  acc1[1] = fma2(hb.x, wa1, acc1[1]);
            acc0[2] = fma2(ha.x, wa2, acc0[2]);  acc1[2] = fma2(hb.x, wa2, acc1[2]);
            acc0[0] = fma2(ha.y, wb0, acc0[0]);  acc1[0] = fma2(hb.y, wb0, acc1[0]);
            acc0[1] = fma2(ha.y, wb1, acc0[1]);  acc1[1] = fma2(hb.y, wb1, acc1[1]);
            acc0[2] = fma2(ha.y, wb2, acc0[2]);  acc1[2] = fma2(hb.y, wb2, acc1[2]);
        }
        // relu + scatter to q/k/v (each pair (j, j+1) computes its own matrix index m)
        #pragma unroll
        for (int p = 0; p < 3; p++) {
            int j  = c0 + 2 * p;
            int m  = j >> 6;
            int jj = j & 63;
            float x0, x1;
            unpack2(acc0[p], x0, x1);
            *(float2*)&qkv[m * (48 * QPAD) + r0 * QPAD + jj] =
                make_float2(fmaxf(x0, 0.0f), fmaxf(x1, 0.0f));
            unpack2(acc1[p], x0, x1);
            *(float2*)&qkv[m * (48 * QPAD) + (r0 + 1) * QPAD + jj] =
                make_float2(fmaxf(x0, 0.0f), fmaxf(x1, 0.0f));
        }
    }
    __syncthreads();

    // ------------------------------------------------------------------
    // Stage 3: preload W15|W16 into Ws head (QKV weights dead). Consumed
    // after the post-attention barrier; LDG latency overlaps attention.
    // ------------------------------------------------------------------
    {
        const float4* W15_4 = (const float4*)W15;
        const float4* W16_4 = (const float4*)W16;
        float4* W4 = (float4*)Ws;
        for (int id = tid; id < 2048; id += NTHR)
            W4[id] = (id < 1024) ? W15_4[id] : W16_4[id - 1024];
    }

    // ------------------------------------------------------------------
    // Stage 4: attention. 2 threads per (t1, head), each owns 24 t2's;
    // shfl_xor(1) combines max / sum / output. Writes aos_dup.
    // ------------------------------------------------------------------
    {
        const int half = tid & 1;
        const int pair = tid >> 1;
        const int head = pair & 7;
        const int t1   = pair >> 3;          // 0..47
        const float* qrow = &qkv[t1 * QPAD + head * 8];
        ulonglong2 qv0 = *(const ulonglong2*)&qrow[0];
        ulonglong2 qv1 = *(const ulonglong2*)&qrow[4];

        const float scale = 0.35355339059327373f;   // 1/sqrt(8)
        const float* kb = &qkv[48 * QPAD + head * 8];
        const int t2b = half * 24;
        float sc[24];
        #pragma unroll
        for (int tt = 0; tt < 24; tt++) {
            const float* kr = &kb[(t2b + tt) * QPAD];
            ulonglong2 kv0 = *(const ulonglong2*)&kr[0];
            ulonglong2 kv1 = *(const ulonglong2*)&kr[4];
            u64 s2 = 0;
            s2 = fma2(qv0.x, kv0.x, s2);
            s2 = fma2(qv0.y, kv0.y, s2);
            s2 = fma2(qv1.x, kv1.x, s2);
            s2 = fma2(qv1.y, kv1.y, s2);
            float lo, hi; unpack2(s2, lo, hi);
            sc[tt] = (lo + hi) * scale;
        }
        float mx = sc[0];
        #pragma unroll
        for (int tt = 1; tt < 24; tt++) mx = fmaxf(mx, sc[tt]);
        mx = fmaxf(mx, __shfl_xor_sync(0xffffffffu, mx, 1));
        float s = 0.0f;
        #pragma unroll
        for (int tt = 0; tt < 24; tt++) {
            float e = __expf(sc[tt] - mx);
            sc[tt] = e;
            s += e;
        }
        float total = s + __shfl_xor_sync(0xffffffffu, s, 1);
        float inv = 1.0f / total;

        u64 o[4] = {0, 0, 0, 0};
        const float* vb = &qkv[2 * 48 * QPAD + head * 8];
        #pragma unroll
        for (int tt = 0; tt < 24; tt++) {
            u64 p2 = pack2(sc[tt], sc[tt]);
            const float* vr = &vb[(t2b + tt) * QPAD];
            ulonglong2 vv0 = *(const ulonglong2*)&vr[0];
            ulonglong2 vv1 = *(const ulonglong2*)&vr[4];
            o[0] = fma2(p2, vv0.x, o[0]);
            o[1] = fma2(p2, vv0.y, o[1]);
            o[2] = fma2(p2, vv1.x, o[2]);
            o[3] = fma2(p2, vv1.y, o[3]);
        }
        // combine halves + duplicated store (each thread stores 2 of 4 pairs)
        #pragma unroll
        for (int j = 0; j < 4; j++) {
            float lo, hi; unpack2(o[j], lo, hi);
            lo += __shfl_xor_sync(0xffffffffu, lo, 1);
            hi += __shfl_xor_sync(0xffffffffu, hi, 1);
            if ((j >> 1) == half) {
                float xl = lo * inv, xh = hi * inv;
                int c = head * 8 + 2 * j;
                aosd[t1 * APAD + c]     = pack2(xl, xl);
                aosd[t1 * APAD + c + 1] = pack2(xh, xh);
            }
        }
    }
    __syncthreads();   // aos_dup ready; W15/W16 loads complete

    // ------------------------------------------------------------------
    // Stage 5: Z = relu(aos @ W15 + b15) -> Zdup (duplicated)
    // Thread tile: 2 rows x 1 col-pair.
    // ------------------------------------------------------------------
    {
        const int r0 = rg * 2;
        const int c0 = cg * 2;
        u64 acc0 = *(const u64*)&b15s[c0];
        u64 acc1 = acc0;
        const u64* ha_base = &aosd[r0 * APAD];
        const u64* hb_base = &aosd[(r0 + 1) * APAD];
        #pragma unroll 4
        for (int k = 0; k < 64; k += 2) {
            ulonglong2 ha = *(const ulonglong2*)&ha_base[k];
            ulonglong2 hb = *(const ulonglong2*)&hb_base[k];
            u64 w0 = *(const u64*)&W15s[k * 64 + c0];
            u64 w1 = *(const u64*)&W15s[(k + 1) * 64 + c0];
            acc0 = fma2(ha.x, w0, acc0);  acc1 = fma2(hb.x, w0, acc1);
            acc0 = fma2(ha.y, w1, acc0);  acc1 = fma2(hb.y, w1, acc1);
        }
        float x0, x1;
        unpack2(acc0, x0, x1);
        x0 = fmaxf(x0, 0.0f); x1 = fmaxf(x1, 0.0f);
        Zdup[r0 * APAD + c0]     = pack2(x0, x0);
        Zdup[r0 * APAD + c0 + 1] = pack2(x1, x1);
        unpack2(acc1, x0, x1);
        x0 = fmaxf(x0, 0.0f); x1 = fmaxf(x1, 0.0f);
        Zdup[(r0 + 1) * APAD + c0]     = pack2(x0, x0);
        Zdup[(r0 + 1) * APAD + c0 + 1] = pack2(x1, x1);
    }
    __syncthreads();

    // ------------------------------------------------------------------
    // Stage 6: out = Z @ W16 + b16 -> global (coalesced float2 stores)
    // ------------------------------------------------------------------
    {
        const int r0 = rg * 2;
        const int c0 = cg * 2;
        u64 acc0 = *(const u64*)&b16s[c0];
        u64 acc1 = acc0;
        const u64* ha_base = &Zdup[r0 * APAD];
        const u64* hb_base = &Zdup[(r0 + 1) * APAD];
        #pragma unroll 4
        for (int k = 0; k < 64; k += 2) {
            ulonglong2 ha = *(const ulonglong2*)&ha_base[k];
            ulonglong2 hb = *(const ulonglong2*)&hb_base[k];
            u64 w0 = *(const u64*)&W16s[k * 64 + c0];
            u64 w1 = *(const u64*)&W16s[(k + 1) * 64 + c0];
            acc0 = fma2(ha.x, w0, acc0);  acc1 = fma2(hb.x, w0, acc1);
            acc0 = fma2(ha.y, w1, acc0);  acc1 = fma2(hb.y, w1, acc1);
        }
        float x0, x1;
        unpack2(acc0, x0, x1);
        *(float2*)&out[((b * T_ + r0) * N_ + n) * 64 + c0] = make_float2(x0, x1);
        unpack2(acc1, x0, x1);
        *(float2*)&out[((b * T_ + r0 + 1) * N_ + n) * 64 + c0] = make_float2(x0, x1);
    }
}

extern "C" void kernel_launch(void* const* d_in, const int* in_sizes, int n_in,
                              void* d_out, int out_size) {
    (void)in_sizes; (void)n_in; (void)out_size;
    cudaFuncSetAttribute(fused_temporal_attn,
                         cudaFuncAttributeMaxDynamicSharedMemorySize, SMEM_BYTES);
    const float* X   = (const float*)d_in[0];
    const float* STE = (const float*)d_in[1];
    const float* W12 = (const float*)d_in[2];
    const float* b12 = (const float*)d_in[3];
    const float* W13 = (const float*)d_in[4];
    const float* b13 = (const float*)d_in[5];
    const float* W14 = (const float*)d_in[6];
    const float* b14 = (const float*)d_in[7];
    const float* W15 = (const float*)d_in[8];
    const float* b15 = (const float*)d_in[9];
    const float* W16 = (const float*)d_in[10];
    const float* b16 = (const float*)d_in[11];
    float* out = (float*)d_out;

    dim3 grid(N_, B_);
    fused_temporal_attn<<<grid, NTHR, SMEM_BYTES>>>(
        X, STE, W12, b12, W13, b13, W14, b14, W15, b15, W16, b16, out);
}

// round 11
// speedup vs baseline: 1.4647x; 1.4647x over previous
#include <cuda_runtime.h>

// TemporalAttentionModel: B=16, T=48, N=500, D=64, K=8 heads, d=8
// Fused per-(b,n) kernel, fp32 FFMA2. 512 threads.
// Attention uses warp-per-(head,part) with pure broadcast K/V reads.

#define B_  16
#define T_  48
#define N_  500
#define NTHR 512

#define HPAD  132   // float stride, H rows      (48 x 132)
#define QPAD  68    // float stride, q/k/v rows  (48 x 68 each)
#define APADU 66    // u64 stride, aos_dup / Z_dup rows (48 x 66)

typedef unsigned long long u64;

__device__ __forceinline__ u64 pack2(float x, float y) {
    u64 r; asm("mov.b64 %0, {%1, %2};" : "=l"(r) : "f"(x), "f"(y)); return r;
}
__device__ __forceinline__ void unpack2(u64 v, float& x, float& y) {
    asm("mov.b64 {%0, %1}, %2;" : "=f"(x), "=f"(y) : "l"(v));
}
__device__ __forceinline__ u64 fma2(u64 a, u64 b, u64 c) {
    u64 d; asm("fma.rn.f32x2 %0, %1, %2, %3;" : "=l"(d) : "l"(a), "l"(b), "l"(c)); return d;
}

// ---- shared memory layout (float units) ----
// [0, 6336)       Hs 48 x HPAD                 -> reused as aos_dup (48 x APADU u64)
// [6336, 30912)   Ws 128 x 192 (QKV weights)   -> reused: W15 [0,4096), W16 [4096,8192),
//                                                 Z_dup (48 x APADU u64) at +8192 floats
// [30912, 40704)  qkv: q | k | v, each 48 x QPAD
// [40704, 41024)  biases: bq 192 | b15 64 | b16 64
#define OFF_WS   6336
#define OFF_QKV  30912
#define OFF_BIAS 40704
static const int SMEM_FLOATS = 41024;
static const int SMEM_BYTES  = SMEM_FLOATS * 4;   // 164,096 B -> 1 CTA/SM

__global__ __launch_bounds__(NTHR, 1)
void fused_temporal_attn(const float* __restrict__ X, const float* __restrict__ STE,
                         const float* __restrict__ W12, const float* __restrict__ b12,
                         const float* __restrict__ W13, const float* __restrict__ b13,
                         const float* __restrict__ W14, const float* __restrict__ b14,
                         const float* __restrict__ W15, const float* __restrict__ b15,
                         const float* __restrict__ W16, const float* __restrict__ b16,
                         float* __restrict__ out)
{
    extern __shared__ float sm[];
    float* Hs    = sm;                      // 48 x HPAD
    float* Ws    = sm + OFF_WS;             // 128 x 192
    float* qkv   = sm + OFF_QKV;            // 3 x 48 x QPAD
    float* biasq = sm + OFF_BIAS;           // 192
    float* b15s  = biasq + 192;             // 64
    float* b16s  = b15s + 64;               // 64
    u64*   aosd  = (u64*)sm;                // 48 x APADU (over Hs after stage 2)
    float* W15s  = Ws;                      // 64 x 64 (after stage 3)
    float* W16s  = Ws + 4096;               // 64 x 64
    u64*   Zdup  = (u64*)(Ws + 8192);       // 48 x APADU

    const int n    = blockIdx.x;
    const int b    = blockIdx.y;
    const int tid  = threadIdx.x;
    const int lane = tid & 31;
    const int warp = tid >> 5;              // 0..15

    // 2-D GEMM tiling: 8 col-subs x 4 row-subs inside a warp
    const int csub = lane & 7;
    const int rsub = lane >> 3;
    const int wc   = warp & 3;
    const int wr   = warp >> 2;
    const int cg   = wc * 8 + csub;         // 0..31
    const int rg   = wr * 4 + rsub;         // 0..15

    // ------------------------------------------------------------------
    // Stage 1: load H, QKV weights, biases
    // ------------------------------------------------------------------
    {
        const float4* X4   = (const float4*)X;
        const float4* STE4 = (const float4*)STE;
        // 768 (X,STE) float4 pairs; threads 0..511 take one, 256 take a 2nd
        for (int id = tid; id < 768; id += NTHR) {
            int t = id >> 4;                // 0..47
            int c = id & 15;                // float4 col
            int base = ((b * T_ + t) * N_ + n) * 16 + c;
            *(float4*)&Hs[t * HPAD + c * 4]      = X4[base];
            *(float4*)&Hs[t * HPAD + 64 + c * 4] = STE4[base];
        }
        // Ws[k*192 + m*64 + j] = Wm[k*64 + j]; 6144 float4, 12/thread
        const float4* Wsrc[3] = { (const float4*)W12, (const float4*)W13, (const float4*)W14 };
        float4* W4 = (float4*)Ws;
        #pragma unroll
        for (int it = 0; it < 12; it++) {
            int id = tid + it * NTHR;
            int k  = id / 48;
            int r  = id - k * 48;
            int m  = r >> 4;
            int j4 = r & 15;
            W4[k * 48 + r] = Wsrc[m][k * 16 + j4];
        }
        if (tid < 64) {
            biasq[tid]       = b12[tid];
            biasq[64 + tid]  = b13[tid];
            biasq[128 + tid] = b14[tid];
            b15s[tid]        = b15[tid];
            b16s[tid]        = b16[tid];
        }
    }
    __syncthreads();

    // ------------------------------------------------------------------
    // Stage 2: QKV = relu(H @ [W12|W13|W14] + bias)  [48 x 192]
    // Thread tile: 3 rows x 6 cols (3 FFMA2 pairs). pack:FFMA2 = 1:3.
    // ------------------------------------------------------------------
    {
        const int r0 = rg * 3;
        const int c0 = cg * 6;
        u64 acc0[3], acc1[3], acc2[3];
        #pragma unroll
        for (int p = 0; p < 3; p++) {
            u64 bp = *(const u64*)&biasq[c0 + 2 * p];
            acc0[p] = bp; acc1[p] = bp; acc2[p] = bp;
        }
        const float* h0 = &Hs[r0 * HPAD];
        const float* h1 = h0 + HPAD;
        const float* h2 = h1 + HPAD;

        #pragma unroll 2
        for (int i = 0; i < 128; i += 4) {
            float ha[4], hb[4], hc[4];
            *(float4*)ha = *(const float4*)&h0[i];
            *(float4*)hb = *(const float4*)&h1[i];
            *(float4*)hc = *(const float4*)&h2[i];
            #pragma unroll
            for (int ii = 0; ii < 4; ii++) {
                const float* wrow = &Ws[(i + ii) * 192 + c0];
                u64 w0 = *(const u64*)&wrow[0];
                u64 w1 = *(const u64*)&wrow[2];
                u64 w2 = *(const u64*)&wrow[4];
                u64 pa = pack2(ha[ii], ha[ii]);
                u64 pb = pack2(hb[ii], hb[ii]);
                u64 pc = pack2(hc[ii], hc[ii]);
                acc0[0] = fma2(pa, w0, acc0[0]);
                acc0[1] = fma2(pa, w1, acc0[1]);
                acc0[2] = fma2(pa, w2, acc0[2]);
                acc1[0] = fma2(pb, w0, acc1[0]);
                acc1[1] = fma2(pb, w1, acc1[1]);
                acc1[2] = fma2(pb, w2, acc1[2]);
                acc2[0] = fma2(pc, w0, acc2[0]);
                acc2[1] = fma2(pc, w1, acc2[1]);
                acc2[2] = fma2(pc, w2, acc2[2]);
            }
        }
        // relu + scatter into q/k/v (pair j even: never straddles a 64-col boundary)
        #pragma unroll
        for (int p = 0; p < 3; p++) {
            int j  = c0 + 2 * p;
            int m  = j >> 6;
            int jj = j & 63;
            float* dst = &qkv[m * (T_ * QPAD) + jj];
            float x0, x1;
            unpack2(acc0[p], x0, x1);
            *(float2*)&dst[(r0)     * QPAD] = make_float2(fmaxf(x0, 0.f), fmaxf(x1, 0.f));
            unpack2(acc1[p], x0, x1);
            *(float2*)&dst[(r0 + 1) * QPAD] = make_float2(fmaxf(x0, 0.f), fmaxf(x1, 0.f));
            unpack2(acc2[p], x0, x1);
            *(float2*)&dst[(r0 + 2) * QPAD] = make_float2(fmaxf(x0, 0.f), fmaxf(x1, 0.f));
        }
    }
    __syncthreads();

    // ------------------------------------------------------------------
    // Stage 3: preload W15|W16 into Ws head (QKV weights dead).
    // Overlaps LDG latency with attention; consumed after next barrier.
    // ------------------------------------------------------------------
    {
        const float4* W15_4 = (const float4*)W15;
        const float4* W16_4 = (const float4*)W16;
        float4* W4 = (float4*)Ws;
        #pragma unroll
        for (int it = 0; it < 4; it++) {
            int id = tid + it * NTHR;
            W4[id] = (id < 1024) ? W15_4[id] : W16_4[id - 1024];
        }
    }

    // ------------------------------------------------------------------
    // Stage 4: attention. warp -> (head = warp>>1, part = warp&1),
    // lane -> t1 = part*32 + lane (valid if < 48). All K/V reads are
    // warp-uniform broadcasts: zero bank conflicts, 1 wavefront each.
    // Each lane owns the full softmax row (no shfl). Writes aos_dup.
    // ------------------------------------------------------------------
    {
        const int head = warp >> 1;
        const int part = warp & 1;
        const int t1   = part * 32 + lane;
        if (t1 < T_) {
            const float* qrow = &qkv[t1 * QPAD + head * 8];
            ulonglong2 q01 = *(const ulonglong2*)&qrow[0];
            ulonglong2 q23 = *(const ulonglong2*)&qrow[4];

            const float scale = 0.35355339059327373f;  // 1/sqrt(8)
            const float* Kb = qkv + T_ * QPAD + head * 8;
            const float* Vb = qkv + 2 * T_ * QPAD + head * 8;

            float sc[T_];
            #pragma unroll
            for (int t2 = 0; t2 < T_; t2++) {
                const float* kr = &Kb[t2 * QPAD];
                ulonglong2 k01 = *(const ulonglong2*)&kr[0];   // broadcast
                ulonglong2 k23 = *(const ulonglong2*)&kr[4];   // broadcast
                u64 s2 = 0;
                s2 = fma2(q01.x, k01.x, s2);
                s2 = fma2(q01.y, k01.y, s2);
                s2 = fma2(q23.x, k23.x, s2);
                s2 = fma2(q23.y, k23.y, s2);
                float lo, hi; unpack2(s2, lo, hi);
                sc[t2] = (lo + hi) * scale;
            }
            float mx = sc[0];
            #pragma unroll
            for (int t2 = 1; t2 < T_; t2++) mx = fmaxf(mx, sc[t2]);
            float s = 0.0f;
            #pragma unroll
            for (int t2 = 0; t2 < T_; t2++) {
                float e = __expf(sc[t2] - mx);
                sc[t2] = e;
                s += e;
            }
            float inv = 1.0f / s;

            u64 o[4] = {0, 0, 0, 0};
            #pragma unroll
            for (int t2 = 0; t2 < T_; t2++) {
                u64 p2 = pack2(sc[t2], sc[t2]);
                const float* vr = &Vb[t2 * QPAD];
                ulonglong2 v01 = *(const ulonglong2*)&vr[0];   // broadcast
                ulonglong2 v23 = *(const ulonglong2*)&vr[4];   // broadcast
                o[0] = fma2(p2, v01.x, o[0]);
                o[1] = fma2(p2, v01.y, o[1]);
                o[2] = fma2(p2, v23.x, o[2]);
                o[3] = fma2(p2, v23.y, o[3]);
            }
            // duplicated store into aos_dup
            u64* dst = &aosd[t1 * APADU + head * 8];
            #pragma unroll
            for (int j = 0; j < 4; j++) {
                float lo, hi; unpack2(o[j], lo, hi);
                lo *= inv; hi *= inv;
                *(ulonglong2*)&dst[2 * j] = make_ulonglong2(pack2(lo, lo), pack2(hi, hi));
            }
        }
    }
    __syncthreads();   // aos_dup ready; W15/W16 loads complete

    // ------------------------------------------------------------------
    // Stage 5: Z = relu(aos @ W15 + b15) -> Z_dup.
    // Thread tile: 3 rows x 1 col-pair. Duplicated activations: no packs.
    // ------------------------------------------------------------------
    {
        const int r0 = rg * 3;
        const int c0 = cg * 2;
        u64 a0 = *(const u64*)&b15s[c0];
        u64 a1 = a0, a2 = a0;
        const u64* x0 = &aosd[r0 * APADU];
        const u64* x1 = x0 + APADU;
        const u64* x2 = x1 + APADU;
        #pragma unroll 4
        for (int k = 0; k < 64; k += 2) {
            ulonglong2 v0 = *(const ulonglong2*)&x0[k];
            ulonglong2 v1 = *(const ulonglong2*)&x1[k];
            ulonglong2 v2 = *(const ulonglong2*)&x2[k];
            u64 w0 = *(const u64*)&W15s[k * 64 + c0];
            u64 w1 = *(const u64*)&W15s[(k + 1) * 64 + c0];
            a0 = fma2(v0.x, w0, a0);  a0 = fma2(v0.y, w1, a0);
            a1 = fma2(v1.x, w0, a1);  a1 = fma2(v1.y, w1, a1);
            a2 = fma2(v2.x, w0, a2);  a2 = fma2(v2.y, w1, a2);
        }
        float x, y;
        unpack2(a0, x, y); x = fmaxf(x, 0.f); y = fmaxf(y, 0.f);
        *(ulonglong2*)&Zdup[(r0)     * APADU + c0] = make_ulonglong2(pack2(x, x), pack2(y, y));
        unpack2(a1, x, y); x = fmaxf(x, 0.f); y = fmaxf(y, 0.f);
        *(ulonglong2*)&Zdup[(r0 + 1) * APADU + c0] = make_ulonglong2(pack2(x, x), pack2(y, y));
        unpack2(a2, x, y); x = fmaxf(x, 0.f); y = fmaxf(y, 0.f);
        *(ulonglong2*)&Zdup[(r0 + 2) * APADU + c0] = make_ulonglong2(pack2(x, x), pack2(y, y));
    }
    __syncthreads();

    // ------------------------------------------------------------------
    // Stage 6: out = Z @ W16 + b16 -> global (float2 stores)
    // ------------------------------------------------------------------
    {
        const int r0 = rg * 3;
        const int c0 = cg * 2;
        u64 a0 = *(const u64*)&b16s[c0];
        u64 a1 = a0, a2 = a0;
        const u64* x0 = &Zdup[r0 * APADU];
        const u64* x1 = x0 + APADU;
        const u64* x2 = x1 + APADU;
        #pragma unroll 4
        for (int k = 0; k < 64; k += 2) {
            ulonglong2 v0 = *(const ulonglong2*)&x0[k];
            ulonglong2 v1 = *(const ulonglong2*)&x1[k];
            ulonglong2 v2 = *(const ulonglong2*)&x2[k];
            u64 w0 = *(const u64*)&W16s[k * 64 + c0];
            u64 w1 = *(const u64*)&W16s[(k + 1) * 64 + c0];
            a0 = fma2(v0.x, w0, a0);  a0 = fma2(v0.y, w1, a0);
            a1 = fma2(v1.x, w0, a1);  a1 = fma2(v1.y, w1, a1);
            a2 = fma2(v2.x, w0, a2);  a2 = fma2(v2.y, w1, a2);
        }
        float x, y;
        unpack2(a0, x, y);
        *(float2*)&out[((b * T_ + r0)     * N_ + n) * 64 + c0] = make_float2(x, y);
        unpack2(a1, x, y);
        *(float2*)&out[((b * T_ + r0 + 1) * N_ + n) * 64 + c0] = make_float2(x, y);
        unpack2(a2, x, y);
        *(float2*)&out[((b * T_ + r0 + 2) * N_ + n) * 64 + c0] = make_float2(x, y);
    }
}

extern "C" void kernel_launch(void* const* d_in, const int* in_sizes, int n_in,
                              void* d_out, int out_size) {
    (void)in_sizes; (void)n_in; (void)out_size;
    cudaFuncSetAttribute(fused_temporal_attn,
                         cudaFuncAttributeMaxDynamicSharedMemorySize, SMEM_BYTES);
    const float* X   = (const float*)d_in[0];
    const float* STE = (const float*)d_in[1];
    const float* W12 = (const float*)d_in[2];
    const float* b12 = (const float*)d_in[3];
    const float* W13 = (const float*)d_in[4];
    const float* b13 = (const float*)d_in[5];
    const float* W14 = (const float*)d_in[6];
    const float* b14 = (const float*)d_in[7];
    const float* W15 = (const float*)d_in[8];
    const float* b15 = (const float*)d_in[9];
    const float* W16 = (const float*)d_in[10];
    const float* b16 = (const float*)d_in[11];
    float* out = (float*)d_out;

    dim3 grid(N_, B_);
    fused_temporal_attn<<<grid, NTHR, SMEM_BYTES>>>(
        X, STE, W12, b12, W13, b13, W14, b14, W15, b15, W16, b16, out);
}

// round 13
// speedup vs baseline: 1.8521x; 1.2645x over previous
#include <cuda_runtime.h>

// TemporalAttentionModel: B=16, T=48, N=500, D=64, K=8 heads, d=8
// Fused per-(b,n) kernel, fp32 FFMA2. 256 threads, 2 CTAs/SM.
// QKV weights streamed in two 64-row halves through a 49KB smem buffer.
// Stage-2 thread tile 6x6 (weight LDS amortized over 6 rows).

#define B_  16
#define T_  48
#define N_  500
#define NTHR 256

#define HPAD  132   // float stride, H rows      (48 x 132)
#define QPAD  68    // float stride, q/k/v rows  (48 x 68 each)
#define APADU 66    // u64 stride, aos_dup / Z_dup rows (48 x 66)

typedef unsigned long long u64;

__device__ __forceinline__ u64 pack2(float x, float y) {
    u64 r; asm("mov.b64 %0, {%1, %2};" : "=l"(r) : "f"(x), "f"(y)); return r;
}
__device__ __forceinline__ void unpack2(u64 v, float& x, float& y) {
    asm("mov.b64 {%0, %1}, %2;" : "=f"(x), "=f"(y) : "l"(v));
}
__device__ __forceinline__ u64 fma2(u64 a, u64 b, u64 c) {
    u64 d; asm("fma.rn.f32x2 %0, %1, %2, %3;" : "=l"(d) : "l"(a), "l"(b), "l"(c)); return d;
}

// ---- shared memory layout (float units) ----
// [0, 6336)       Hs 48 x HPAD            -> reused as aos_dup (48 x APADU u64)
// [6336, 18624)   Wbuf 64 x 192 (one weight k-half)
//                   -> later: W15 [0,4096), W16 [4096,8192),
//                      Z_dup (48 x APADU u64 = 12672 fl) at Wbuf+8192
//                      (spans [14528, 27200) fl: dead Wbuf tail + dead qkv)
// [18624, 28416)  qkv: q | k | v, each 48 x QPAD  (dead when Z_dup written)
// [28416, 28736)  biases: bq 192 | b15 64 | b16 64
#define OFF_WB   6336
#define OFF_QKV  18624
#define OFF_BIAS 28416
static const int SMEM_FLOATS = 28736;
static const int SMEM_BYTES  = SMEM_FLOATS * 4;   // 114,944 B -> 2 CTAs/SM

__global__ __launch_bounds__(NTHR, 2)
void fused_temporal_attn(const float* __restrict__ X, const float* __restrict__ STE,
                         const float* __restrict__ W12, const float* __restrict__ b12,
                         const float* __restrict__ W13, const float* __restrict__ b13,
                         const float* __restrict__ W14, const float* __restrict__ b14,
                         const float* __restrict__ W15, const float* __restrict__ b15,
                         const float* __restrict__ W16, const float* __restrict__ b16,
                         float* __restrict__ out)
{
    extern __shared__ float sm[];
    float* Hs    = sm;                      // 48 x HPAD
    float* Wbuf  = sm + OFF_WB;             // 64 x 192 (streamed halves)
    float* qkv   = sm + OFF_QKV;            // 3 x 48 x QPAD
    float* biasq = sm + OFF_BIAS;           // 192
    float* b15s  = biasq + 192;             // 64
    float* b16s  = b15s + 64;               // 64
    u64*   aosd  = (u64*)sm;                // 48 x APADU (over Hs after stage 2)
    float* W15s  = Wbuf;                    // 64 x 64 (after stage 3)
    float* W16s  = Wbuf + 4096;             // 64 x 64
    u64*   Zdup  = (u64*)(Wbuf + 8192);     // 48 x APADU (dead Wbuf tail + dead qkv)

    const int n    = blockIdx.x;
    const int b    = blockIdx.y;
    const int tid  = threadIdx.x;
    const int lane = tid & 31;
    const int warp = tid >> 5;              // 0..7

    const int csub = lane & 7;
    const int rsub = lane >> 3;
    const int wc   = warp & 3;
    const int wr   = warp >> 2;             // 0..1
    const int cg   = wc * 8 + csub;         // 0..31
    const int rg   = wr * 4 + rsub;         // 0..7

    const float4* Wsrc[3] = { (const float4*)W12, (const float4*)W13, (const float4*)W14 };
    float4* WB4 = (float4*)Wbuf;

    // ------------------------------------------------------------------
    // Stage 1: load H, weight half 0 (k = 0..63), biases
    // ------------------------------------------------------------------
    {
        const float4* X4   = (const float4*)X;
        const float4* STE4 = (const float4*)STE;
        #pragma unroll
        for (int it = 0; it < 3; it++) {
            int id = tid + it * NTHR;       // 0..767
            int t = id >> 4;
            int c = id & 15;
            int base = ((b * T_ + t) * N_ + n) * 16 + c;
            *(float4*)&Hs[t * HPAD + c * 4]      = X4[base];
            *(float4*)&Hs[t * HPAD + 64 + c * 4] = STE4[base];
        }
        #pragma unroll
        for (int it = 0; it < 12; it++) {
            int id = tid + it * NTHR;       // 0..3071
            int k  = id / 48;
            int r  = id - k * 48;
            int m  = r >> 4;
            int j4 = r & 15;
            WB4[k * 48 + r] = Wsrc[m][k * 16 + j4];
        }
        if (tid < 64) {
            biasq[tid]       = b12[tid];
            biasq[64 + tid]  = b13[tid];
            biasq[128 + tid] = b14[tid];
            b15s[tid]        = b15[tid];
            b16s[tid]        = b16[tid];
        }
    }
    __syncthreads();

    // ------------------------------------------------------------------
    // Stage 2: QKV = relu(H @ [W12|W13|W14] + bias), k streamed in halves.
    // Thread tile: 6 rows x 6 cols (weight LDS reused across 6 rows).
    // ------------------------------------------------------------------
    const int r0  = rg * 6;
    const int c0q = cg * 6;
    u64 acc[6][3];
    #pragma unroll
    for (int p = 0; p < 3; p++) {
        u64 bp = *(const u64*)&biasq[c0q + 2 * p];
        #pragma unroll
        for (int r = 0; r < 6; r++) acc[r][p] = bp;
    }

    auto compute_chunk = [&](int koff) {
        #pragma unroll 2
        for (int i = 0; i < 64; i += 4) {
            float h[6][4];
            #pragma unroll
            for (int r = 0; r < 6; r++)
                *(float4*)h[r] = *(const float4*)&Hs[(r0 + r) * HPAD + koff + i];
            #pragma unroll
            for (int ii = 0; ii < 4; ii++) {
                const float* wrow = &Wbuf[(i + ii) * 192 + c0q];
                u64 w0 = *(const u64*)&wrow[0];
                u64 w1 = *(const u64*)&wrow[2];
                u64 w2 = *(const u64*)&wrow[4];
                #pragma unroll
                for (int r = 0; r < 6; r++) {
                    u64 p = pack2(h[r][ii], h[r][ii]);
                    acc[r][0] = fma2(p, w0, acc[r][0]);
                    acc[r][1] = fma2(p, w1, acc[r][1]);
                    acc[r][2] = fma2(p, w2, acc[r][2]);
                }
            }
        }
    };

    compute_chunk(0);
    __syncthreads();                        // done reading weight half 0
    // load weight half 1 (k = 64..127)
    #pragma unroll
    for (int it = 0; it < 12; it++) {
        int id = tid + it * NTHR;
        int k  = id / 48;
        int r  = id - k * 48;
        int m  = r >> 4;
        int j4 = r & 15;
        WB4[k * 48 + r] = Wsrc[m][(64 + k) * 16 + j4];
    }
    __syncthreads();                        // half 1 visible
    compute_chunk(64);

    // relu + scatter into q/k/v (pair j even: never straddles a 64-col boundary)
    #pragma unroll
    for (int p = 0; p < 3; p++) {
        int j  = c0q + 2 * p;
        int m  = j >> 6;
        int jj = j & 63;
        float* dst = &qkv[m * (T_ * QPAD) + jj];
        #pragma unroll
        for (int r = 0; r < 6; r++) {
            float x0, x1;
            unpack2(acc[r][p], x0, x1);
            *(float2*)&dst[(r0 + r) * QPAD] = make_float2(fmaxf(x0, 0.f), fmaxf(x1, 0.f));
        }
    }
    __syncthreads();                        // qkv ready; Wbuf dead

    // ------------------------------------------------------------------
    // Stage 3: preload W15|W16 into Wbuf[0,8192). LDG latency overlaps
    // attention; consumed after the post-attention barrier.
    // ------------------------------------------------------------------
    {
        const float4* W15_4 = (const float4*)W15;
        const float4* W16_4 = (const float4*)W16;
        #pragma unroll
        for (int it = 0; it < 8; it++) {
            int id = tid + it * NTHR;       // 0..2047
            WB4[id] = (id < 1024) ? W15_4[id] : W16_4[id - 1024];
        }
    }

    // ------------------------------------------------------------------
    // Stage 4: attention. warp = head (8 warps), two t1 passes:
    // t1 = lane, then t1 = 32+lane (lane<16). All K/V reads warp-uniform
    // broadcasts (1 wavefront, conflict-free). Writes aos_dup.
    // ------------------------------------------------------------------
    {
        const int head = warp;
        const float scale = 0.35355339059327373f;   // 1/sqrt(8)
        const float* Kb = qkv + T_ * QPAD + head * 8;
        const float* Vb = qkv + 2 * T_ * QPAD + head * 8;

        #pragma unroll 1
        for (int pass = 0; pass < 2; pass++) {
            int t1 = pass * 32 + lane;
            if (t1 < T_) {
                const float* qrow = &qkv[t1 * QPAD + head * 8];
                ulonglong2 q01 = *(const ulonglong2*)&qrow[0];
                ulonglong2 q23 = *(const ulonglong2*)&qrow[4];

                float sc[T_];
                #pragma unroll
                for (int t2 = 0; t2 < T_; t2++) {
                    const float* kr = &Kb[t2 * QPAD];
                    ulonglong2 k01 = *(const ulonglong2*)&kr[0];   // broadcast
                    ulonglong2 k23 = *(const ulonglong2*)&kr[4];   // broadcast
                    u64 s2 = 0;
                    s2 = fma2(q01.x, k01.x, s2);
                    s2 = fma2(q01.y, k01.y, s2);
                    s2 = fma2(q23.x, k23.x, s2);
                    s2 = fma2(q23.y, k23.y, s2);
                    float lo, hi; unpack2(s2, lo, hi);
                    sc[t2] = (lo + hi) * scale;
                }
                float mx = sc[0];
                #pragma unroll
                for (int t2 = 1; t2 < T_; t2++) mx = fmaxf(mx, sc[t2]);
                float s = 0.0f;
                #pragma unroll
                for (int t2 = 0; t2 < T_; t2++) {
                    float e = __expf(sc[t2] - mx);
                    sc[t2] = e;
                    s += e;
                }
                float inv = 1.0f / s;

                u64 o[4] = {0, 0, 0, 0};
                #pragma unroll
                for (int t2 = 0; t2 < T_; t2++) {
                    u64 p2 = pack2(sc[t2], sc[t2]);
                    const float* vr = &Vb[t2 * QPAD];
                    ulonglong2 v01 = *(const ulonglong2*)&vr[0];   // broadcast
                    ulonglong2 v23 = *(const ulonglong2*)&vr[4];   // broadcast
                    o[0] = fma2(p2, v01.x, o[0]);
                    o[1] = fma2(p2, v01.y, o[1]);
                    o[2] = fma2(p2, v23.x, o[2]);
                    o[3] = fma2(p2, v23.y, o[3]);
                }
                u64* dst = &aosd[t1 * APADU + head * 8];
                #pragma unroll
                for (int j = 0; j < 4; j++) {
                    float lo, hi; unpack2(o[j], lo, hi);
                    lo *= inv; hi *= inv;
                    *(ulonglong2*)&dst[2 * j] = make_ulonglong2(pack2(lo, lo), pack2(hi, hi));
                }
            }
        }
    }
    __syncthreads();   // aos_dup ready; W15/W16 ready; qkv + Wbuf tail dead

    // ------------------------------------------------------------------
    // Stage 5: Z = relu(aos @ W15 + b15) -> Z_dup (dead Wbuf tail + qkv).
    // Thread tile: 6 rows x 1 col-pair. Duplicated activations: no packs.
    // ------------------------------------------------------------------
    const int c0 = cg * 2;
    {
        u64 a[6];
        u64 bz = *(const u64*)&b15s[c0];
        #pragma unroll
        for (int r = 0; r < 6; r++) a[r] = bz;
        #pragma unroll 4
        for (int k = 0; k < 64; k += 2) {
            u64 w0 = *(const u64*)&W15s[k * 64 + c0];
            u64 w1 = *(const u64*)&W15s[(k + 1) * 64 + c0];
            #pragma unroll
            for (int r = 0; r < 6; r++) {
                ulonglong2 v = *(const ulonglong2*)&aosd[(r0 + r) * APADU + k];
                a[r] = fma2(v.x, w0, a[r]);
                a[r] = fma2(v.y, w1, a[r]);
            }
        }
        #pragma unroll
        for (int r = 0; r < 6; r++) {
            float x, y;
            unpack2(a[r], x, y);
            x = fmaxf(x, 0.f); y = fmaxf(y, 0.f);
            *(ulonglong2*)&Zdup[(r0 + r) * APADU + c0] =
                make_ulonglong2(pack2(x, x), pack2(y, y));
        }
    }
    __syncthreads();

    // ------------------------------------------------------------------
    // Stage 6: out = Z @ W16 + b16 -> global (float2 stores)
    // ------------------------------------------------------------------
    {
        u64 a[6];
        u64 bz = *(const u64*)&b16s[c0];
        #pragma unroll
        for (int r = 0; r < 6; r++) a[r] = bz;
        #pragma unroll 4
        for (int k = 0; k < 64; k += 2) {
            u64 w0 = *(const u64*)&W16s[k * 64 + c0];
            u64 w1 = *(const u64*)&W16s[(k + 1) * 64 + c0];
            #pragma unroll
            for (int r = 0; r < 6; r++) {
                ulonglong2 v = *(const ulonglong2*)&Zdup[(r0 + r) * APADU + k];
                a[r] = fma2(v.x, w0, a[r]);
                a[r] = fma2(v.y, w1, a[r]);
            }
        }
        #pragma unroll
        for (int r = 0; r < 6; r++) {
            float x, y;
            unpack2(a[r], x, y);
            *(float2*)&out[((b * T_ + r0 + r) * N_ + n) * 64 + c0] = make_float2(x, y);
        }
    }
}

extern "C" void kernel_launch(void* const* d_in, const int* in_sizes, int n_in,
                              void* d_out, int out_size) {
    (void)in_sizes; (void)n_in; (void)out_size;
    cudaFuncSetAttribute(fused_temporal_attn,
                         cudaFuncAttributeMaxDynamicSharedMemorySize, SMEM_BYTES);
    const float* X   = (const float*)d_in[0];
    const float* STE = (const float*)d_in[1];
    const float* W12 = (const float*)d_in[2];
    const float* b12 = (const float*)d_in[3];
    const float* W13 = (const float*)d_in[4];
    const float* b13 = (const float*)d_in[5];
    const float* W14 = (const float*)d_in[6];
    const float* b14 = (const float*)d_in[7];
    const float* W15 = (const float*)d_in[8];
    const float* b15 = (const float*)d_in[9];
    const float* W16 = (const float*)d_in[10];
    const float* b16 = (const float*)d_in[11];
    float* out = (float*)d_out;

    dim3 grid(N_, B_);
    fused_temporal_attn<<<grid, NTHR, SMEM_BYTES>>>(
        X, STE, W12, b12, W13, b13, W14, b14, W15, b15, W16, b16, out);
}